// round 2
// baseline (speedup 1.0000x reference)
#include <cuda_runtime.h>
#include <cuda_bf16.h>
#include <cstdint>

// Problem constants (fixed by the reference setup)
#define N_NODES 250000
#define N_EDGES 4000000
#define NODE_F  4
#define HID     32
#define NN      50
#define NF      3
#define D_IN    9      // 2*NODE_F + 1
#define D_CAT   36     // NODE_F + HID
#define OUT_C   53     // NN + NF

// Scratch (device globals; no allocations allowed)
__device__ __align__(16) float g_Hagg[(size_t)N_NODES * HID];  // 32 MB
__device__ float g_deg[N_NODES];
__device__ float g_conc[N_NODES];
__device__ float g_S;
__device__ int   g_ei_is64;

__device__ __forceinline__ float softplusf(float x) {
    return fmaxf(x, 0.0f) + log1pf(expf(-fabsf(x)));
}

// ---------------------------------------------------------------------------
// Kernel -1: detect edge_index dtype (int64 -> odd 32-bit words all zero)
// ---------------------------------------------------------------------------
__global__ void detect_kernel(const int* __restrict__ ei32) {
    int z = 0;
    #pragma unroll
    for (int i = 1; i < 64; i += 2) z |= ei32[i];
    g_ei_is64 = (z == 0) ? 1 : 0;
}

// ---------------------------------------------------------------------------
// Kernel 0: zero the scratch buffers
// ---------------------------------------------------------------------------
__global__ void zero_kernel() {
    const int tid = blockIdx.x * blockDim.x + threadIdx.x;
    const int stride = gridDim.x * blockDim.x;
    float4* p = reinterpret_cast<float4*>(g_Hagg);
    const int nv4 = (N_NODES * HID) / 4;
    for (int i = tid; i < nv4; i += stride) p[i] = make_float4(0.f, 0.f, 0.f, 0.f);
    for (int i = tid; i < N_NODES; i += stride) g_deg[i] = 0.f;
    if (tid == 0) g_S = 0.f;
}

// ---------------------------------------------------------------------------
// Kernel 1: per-edge MLP layer-1 + segment-sum of hidden (W2 deferred)
// ---------------------------------------------------------------------------
__global__ __launch_bounds__(256) void edge_kernel(
    const float* __restrict__ x,
    const void* __restrict__ ei_raw,
    const float* __restrict__ ea,
    const float* __restrict__ W1,
    const float* __restrict__ b1)
{
    __shared__ float sW1[D_IN * HID];
    __shared__ float sb1[HID];
    for (int i = threadIdx.x; i < D_IN * HID; i += blockDim.x) sW1[i] = W1[i];
    for (int i = threadIdx.x; i < HID; i += blockDim.x) sb1[i] = b1[i];
    __syncthreads();

    const int e = blockIdx.x * blockDim.x + threadIdx.x;
    if (e >= N_EDGES) return;

    int r, c;
    if (g_ei_is64) {
        const long long* ei = (const long long*)ei_raw;
        r = (int)__ldg(ei + e);
        c = (int)__ldg(ei + N_EDGES + e);
    } else {
        const int* ei = (const int*)ei_raw;
        r = __ldg(ei + e);
        c = __ldg(ei + N_EDGES + e);
    }

    const float4 xr = __ldg(reinterpret_cast<const float4*>(x) + r);
    const float4 xc = __ldg(reinterpret_cast<const float4*>(x) + c);
    const float a0 = __ldg(ea + e);

    float in[D_IN] = {xr.x, xr.y, xr.z, xr.w, xc.x, xc.y, xc.z, xc.w, a0};

    float h[HID];
    #pragma unroll
    for (int j = 0; j < HID; j++) {
        float acc = sb1[j];
        #pragma unroll
        for (int d = 0; d < D_IN; d++) acc = fmaf(in[d], sW1[d * HID + j], acc);
        h[j] = fmaxf(acc, 0.0f);
    }

    float* dst = g_Hagg + (size_t)r * HID;
    #pragma unroll
    for (int k = 0; k < HID / 4; k++) {
        asm volatile("red.global.add.v4.f32 [%0], {%1, %2, %3, %4};"
                     :: "l"(dst + 4 * k),
                        "f"(h[4 * k + 0]), "f"(h[4 * k + 1]),
                        "f"(h[4 * k + 2]), "f"(h[4 * k + 3])
                     : "memory");
    }
    atomicAdd(&g_deg[r], 1.0f);
}

// ---------------------------------------------------------------------------
// Kernel 2: per-node (one warp per node)
// ---------------------------------------------------------------------------
__global__ __launch_bounds__(256) void node_kernel(
    const float* __restrict__ x,
    const float* __restrict__ W2,  const float* __restrict__ b2,
    const float* __restrict__ Wc,  const float* __restrict__ bc,
    const float* __restrict__ Wmu, const float* __restrict__ bmu,
    const float* __restrict__ Wsig,const float* __restrict__ bsig,
    const float* __restrict__ high,
    float* __restrict__ out)
{
    __shared__ float sW2[HID * HID];
    __shared__ float sWc[D_CAT], sWmu[D_CAT], sWsig[D_CAT];
    __shared__ float sb2[HID];
    __shared__ float sBlockSum[8];

    for (int i = threadIdx.x; i < HID * HID; i += blockDim.x) sW2[i] = W2[i];
    if (threadIdx.x < D_CAT) {
        sWc[threadIdx.x]   = Wc[threadIdx.x];
        sWmu[threadIdx.x]  = Wmu[threadIdx.x];
        sWsig[threadIdx.x] = Wsig[threadIdx.x];
    }
    if (threadIdx.x < HID) sb2[threadIdx.x] = b2[threadIdx.x];
    __syncthreads();

    const int warp = threadIdx.x >> 5;
    const int lane = threadIdx.x & 31;
    const int node = blockIdx.x * (blockDim.x >> 5) + warp;

    float concv = 0.0f;
    if (node < N_NODES) {
        const float hk = g_Hagg[(size_t)node * HID + lane];
        const float d  = g_deg[node];

        float v = d * sb2[lane];
        #pragma unroll
        for (int k = 0; k < HID; k++) {
            const float hb = __shfl_sync(0xffffffffu, hk, k);
            v = fmaf(hb, sW2[k * HID + lane], v);
        }

        const int p = node % NN;
        const bool tail = (p >= NN - NF);

        float pc = v * sWc[NODE_F + lane];
        float pm = tail ? v * sWmu[NODE_F + lane]  : 0.0f;
        float ps = tail ? v * sWsig[NODE_F + lane] : 0.0f;
        #pragma unroll
        for (int off = 16; off > 0; off >>= 1) {
            pc += __shfl_xor_sync(0xffffffffu, pc, off);
            pm += __shfl_xor_sync(0xffffffffu, pm, off);
            ps += __shfl_xor_sync(0xffffffffu, ps, off);
        }

        const float4 xi = __ldg(reinterpret_cast<const float4*>(x) + node);
        const float xcpart = xi.x * sWc[0] + xi.y * sWc[1] + xi.z * sWc[2] + xi.w * sWc[3];
        const float craw = pc + xcpart + bc[0] + 1e-10f;
        concv = softplusf(craw);
        if (lane == 0) {
            g_conc[node] = concv;
            if (tail) {
                const float xm = xi.x * sWmu[0] + xi.y * sWmu[1] + xi.z * sWmu[2] + xi.w * sWmu[3];
                const float xs = xi.x * sWsig[0] + xi.y * sWsig[1] + xi.z * sWsig[2] + xi.w * sWsig[3];
                const float mraw = pm + xm + bmu[0] + 1e-20f;
                const float sraw = ps + xs + bsig[0] + 1e-20f;
                const float alpha = softplusf(mraw) + 1e-20f;
                const float beta  = softplusf(sraw) + 1e-20f;
                const int g = node / NN;
                const int j = p - (NN - NF);
                out[g * OUT_C + NN + j] = alpha / (alpha + beta) * high[j];
            }
        }
    }

    if (lane == 0) sBlockSum[warp] = (node < N_NODES) ? concv : 0.0f;
    __syncthreads();
    if (threadIdx.x == 0) {
        float s = 0.0f;
        #pragma unroll
        for (int w = 0; w < 8; w++) s += sBlockSum[w];
        atomicAdd(&g_S, s);
    }
}

// ---------------------------------------------------------------------------
// Kernel 3: normalize conc by the global sum
// ---------------------------------------------------------------------------
__global__ void final_kernel(float* __restrict__ out) {
    const int i = blockIdx.x * blockDim.x + threadIdx.x;
    if (i >= N_NODES) return;
    const float invS = 1.0f / (g_S + 1e-20f);
    const int g = i / NN;
    const int p = i % NN;
    out[g * OUT_C + p] = g_conc[i] * invS;
}

// ---------------------------------------------------------------------------
// Entry point
// ---------------------------------------------------------------------------
extern "C" void kernel_launch(void* const* d_in, const int* in_sizes, int n_in,
                              void* d_out, int out_size) {
    const float* x    = (const float*)d_in[0];
    const void*  ei   = d_in[1];
    const float* ea   = (const float*)d_in[2];
    const float* high = (const float*)d_in[3];
    const float* W1   = (const float*)d_in[4];
    const float* b1   = (const float*)d_in[5];
    const float* W2   = (const float*)d_in[6];
    const float* b2   = (const float*)d_in[7];
    const float* Wc   = (const float*)d_in[8];
    const float* bc   = (const float*)d_in[9];
    const float* Wmu  = (const float*)d_in[10];
    const float* bmu  = (const float*)d_in[11];
    const float* Wsig = (const float*)d_in[12];
    const float* bsig = (const float*)d_in[13];
    float* out = (float*)d_out;

    detect_kernel<<<1, 1>>>((const int*)ei);
    zero_kernel<<<1184, 256>>>();
    edge_kernel<<<(N_EDGES + 255) / 256, 256>>>(x, ei, ea, W1, b1);
    node_kernel<<<(N_NODES + 7) / 8, 256>>>(x, W2, b2, Wc, bc, Wmu, bmu, Wsig, bsig, high, out);
    final_kernel<<<(N_NODES + 255) / 256, 256>>>(out);
}

// round 3
// speedup vs baseline: 2.2735x; 2.2735x over previous
#include <cuda_runtime.h>
#include <cuda_bf16.h>
#include <cstdint>

#define N_NODES 250000
#define N_EDGES 4000000
#define NODE_F  4
#define HID     32
#define NN      50
#define NF      3
#define D_IN    9
#define OUT_C   53

// Scratch (device globals)
__device__ __align__(16) float4 g_acc[N_NODES];   // {hc, hm, hs, deg} per node: 4 MB
__device__ float g_conc[N_NODES];
__device__ float g_S;
__device__ int   g_ei_is64;
// Precomputed projections: uc = W2 @ Wc[4:], um = W2 @ Wmu[4:], us = W2 @ Wsig[4:]
__device__ float g_uc[HID], g_um[HID], g_us[HID];
__device__ float g_sc, g_sm, g_ss;                // b2 . W*[4:]

__device__ __forceinline__ float softplusf(float x) {
    return fmaxf(x, 0.0f) + log1pf(expf(-fabsf(x)));
}

// ---------------------------------------------------------------------------
// Kernel A: detect ei dtype + precompute head projections (1 warp)
// ---------------------------------------------------------------------------
__global__ void prep_kernel(const int* __restrict__ ei32,
                            const float* __restrict__ W2,
                            const float* __restrict__ b2,
                            const float* __restrict__ Wc,
                            const float* __restrict__ Wmu,
                            const float* __restrict__ Wsig)
{
    const int k = threadIdx.x;  // 32 threads
    if (k == 0) {
        int z = 0;
        #pragma unroll
        for (int i = 1; i < 64; i += 2) z |= ei32[i];
        g_ei_is64 = (z == 0) ? 1 : 0;
        g_S = 0.0f;
    }
    float uc = 0.f, um = 0.f, us = 0.f;
    #pragma unroll
    for (int j = 0; j < HID; j++) {
        const float w = W2[k * HID + j];
        uc = fmaf(w, Wc[NODE_F + j],   uc);
        um = fmaf(w, Wmu[NODE_F + j],  um);
        us = fmaf(w, Wsig[NODE_F + j], us);
    }
    g_uc[k] = uc; g_um[k] = um; g_us[k] = us;
    // scalar b2 projections via warp reduce
    float pc = b2[k] * Wc[NODE_F + k];
    float pm = b2[k] * Wmu[NODE_F + k];
    float ps = b2[k] * Wsig[NODE_F + k];
    #pragma unroll
    for (int off = 16; off > 0; off >>= 1) {
        pc += __shfl_xor_sync(0xffffffffu, pc, off);
        pm += __shfl_xor_sync(0xffffffffu, pm, off);
        ps += __shfl_xor_sync(0xffffffffu, ps, off);
    }
    if (k == 0) { g_sc = pc; g_sm = pm; g_ss = ps; }
}

// ---------------------------------------------------------------------------
// Kernel B: zero accumulators (4 MB)
// ---------------------------------------------------------------------------
__global__ void zero_kernel() {
    const int i = blockIdx.x * blockDim.x + threadIdx.x;
    if (i < N_NODES) g_acc[i] = make_float4(0.f, 0.f, 0.f, 0.f);
}

// ---------------------------------------------------------------------------
// Kernel C: per-edge layer-1 MLP + projected scatter (one float4 RED per edge)
// ---------------------------------------------------------------------------
__global__ __launch_bounds__(256) void edge_kernel(
    const float* __restrict__ x,
    const void* __restrict__ ei_raw,
    const float* __restrict__ ea,
    const float* __restrict__ W1,
    const float* __restrict__ b1)
{
    __shared__ float sW1[D_IN * HID];
    __shared__ float sb1[HID];
    __shared__ float suc[HID], sum_[HID], sus[HID];
    for (int i = threadIdx.x; i < D_IN * HID; i += blockDim.x) sW1[i] = W1[i];
    if (threadIdx.x < HID) {
        sb1[threadIdx.x]  = b1[threadIdx.x];
        suc[threadIdx.x]  = g_uc[threadIdx.x];
        sum_[threadIdx.x] = g_um[threadIdx.x];
        sus[threadIdx.x]  = g_us[threadIdx.x];
    }
    __syncthreads();

    const int e = blockIdx.x * blockDim.x + threadIdx.x;
    if (e >= N_EDGES) return;

    int r, c;
    if (g_ei_is64) {
        const long long* ei = (const long long*)ei_raw;
        r = (int)__ldg(ei + e);
        c = (int)__ldg(ei + N_EDGES + e);
    } else {
        const int* ei = (const int*)ei_raw;
        r = __ldg(ei + e);
        c = __ldg(ei + N_EDGES + e);
    }

    const float4 xr = __ldg(reinterpret_cast<const float4*>(x) + r);
    const float4 xc = __ldg(reinterpret_cast<const float4*>(x) + c);
    const float a0 = __ldg(ea + e);
    const float in[D_IN] = {xr.x, xr.y, xr.z, xr.w, xc.x, xc.y, xc.z, xc.w, a0};

    float hc = 0.f, hm = 0.f, hs = 0.f;
    #pragma unroll
    for (int j = 0; j < HID; j++) {
        float acc = sb1[j];
        #pragma unroll
        for (int d = 0; d < D_IN; d++) acc = fmaf(in[d], sW1[d * HID + j], acc);
        const float hj = fmaxf(acc, 0.0f);
        hc = fmaf(hj, suc[j],  hc);
        hm = fmaf(hj, sum_[j], hm);
        hs = fmaf(hj, sus[j],  hs);
    }

    asm volatile("red.global.add.v4.f32 [%0], {%1, %2, %3, %4};"
                 :: "l"(&g_acc[r]), "f"(hc), "f"(hm), "f"(hs), "f"(1.0f)
                 : "memory");
}

// ---------------------------------------------------------------------------
// Kernel D: per-node heads + conc sum (one thread per node)
// ---------------------------------------------------------------------------
__global__ __launch_bounds__(256) void node_kernel(
    const float* __restrict__ x,
    const float* __restrict__ Wc,  const float* __restrict__ bc,
    const float* __restrict__ Wmu, const float* __restrict__ bmu,
    const float* __restrict__ Wsig,const float* __restrict__ bsig,
    const float* __restrict__ high,
    float* __restrict__ out)
{
    __shared__ float sWarp[8];
    const int i = blockIdx.x * blockDim.x + threadIdx.x;

    float concv = 0.0f;
    if (i < N_NODES) {
        const float4 a  = g_acc[i];
        const float4 xi = __ldg(reinterpret_cast<const float4*>(x) + i);

        const float craw = xi.x * __ldg(Wc+0) + xi.y * __ldg(Wc+1)
                         + xi.z * __ldg(Wc+2) + xi.w * __ldg(Wc+3)
                         + a.x + a.w * g_sc + __ldg(bc) + 1e-10f;
        concv = softplusf(craw);
        g_conc[i] = concv;

        const int p = i % NN;
        if (p >= NN - NF) {
            const float mraw = xi.x * __ldg(Wmu+0) + xi.y * __ldg(Wmu+1)
                             + xi.z * __ldg(Wmu+2) + xi.w * __ldg(Wmu+3)
                             + a.y + a.w * g_sm + __ldg(bmu) + 1e-20f;
            const float sraw = xi.x * __ldg(Wsig+0) + xi.y * __ldg(Wsig+1)
                             + xi.z * __ldg(Wsig+2) + xi.w * __ldg(Wsig+3)
                             + a.z + a.w * g_ss + __ldg(bsig) + 1e-20f;
            const float alpha = softplusf(mraw) + 1e-20f;
            const float beta  = softplusf(sraw) + 1e-20f;
            const int g = i / NN;
            const int j = p - (NN - NF);
            out[g * OUT_C + NN + j] = alpha / (alpha + beta) * __ldg(high + j);
        }
    }

    // block reduction of conc
    float s = concv;
    #pragma unroll
    for (int off = 16; off > 0; off >>= 1) s += __shfl_xor_sync(0xffffffffu, s, off);
    if ((threadIdx.x & 31) == 0) sWarp[threadIdx.x >> 5] = s;
    __syncthreads();
    if (threadIdx.x == 0) {
        float t = 0.f;
        #pragma unroll
        for (int w = 0; w < 8; w++) t += sWarp[w];
        atomicAdd(&g_S, t);
    }
}

// ---------------------------------------------------------------------------
// Kernel E: normalize conc
// ---------------------------------------------------------------------------
__global__ void final_kernel(float* __restrict__ out) {
    const int i = blockIdx.x * blockDim.x + threadIdx.x;
    if (i >= N_NODES) return;
    const float invS = 1.0f / (g_S + 1e-20f);
    out[(i / NN) * OUT_C + (i % NN)] = g_conc[i] * invS;
}

// ---------------------------------------------------------------------------
extern "C" void kernel_launch(void* const* d_in, const int* in_sizes, int n_in,
                              void* d_out, int out_size) {
    const float* x    = (const float*)d_in[0];
    const void*  ei   = d_in[1];
    const float* ea   = (const float*)d_in[2];
    const float* high = (const float*)d_in[3];
    const float* W1   = (const float*)d_in[4];
    const float* b1   = (const float*)d_in[5];
    const float* W2   = (const float*)d_in[6];
    const float* b2   = (const float*)d_in[7];
    const float* Wc   = (const float*)d_in[8];
    const float* bc   = (const float*)d_in[9];
    const float* Wmu  = (const float*)d_in[10];
    const float* bmu  = (const float*)d_in[11];
    const float* Wsig = (const float*)d_in[12];
    const float* bsig = (const float*)d_in[13];
    float* out = (float*)d_out;

    prep_kernel<<<1, 32>>>((const int*)ei, W2, b2, Wc, Wmu, Wsig);
    zero_kernel<<<(N_NODES + 255) / 256, 256>>>();
    edge_kernel<<<(N_EDGES + 255) / 256, 256>>>(x, ei, ea, W1, b1);
    node_kernel<<<(N_NODES + 255) / 256, 256>>>(x, Wc, bc, Wmu, bmu, Wsig, bsig, high, out);
    final_kernel<<<(N_NODES + 255) / 256, 256>>>(out);
}

// round 4
// speedup vs baseline: 2.6715x; 1.1751x over previous
#include <cuda_runtime.h>
#include <cstdint>

#define N_NODES 250000
#define N_EDGES 4000000
#define NODE_F  4
#define HID     32
#define NN      50
#define NF      3
#define D_IN    9
#define OUT_C   53

typedef unsigned long long u64;

// Scratch (device globals)
__device__ __align__(16) float4 g_acc[N_NODES];   // {hc, hm, hs, deg}: 4 MB
__device__ float g_conc[N_NODES];
__device__ float g_S;
__device__ int   g_ei_is64;
__device__ float g_sc, g_sm, g_ss;                // b2 . W*[4:36] scalars
// Packed per-j weight record: slots [0..8]=W1 col j (dup), [9]=b1, [10..12]=0.5*{uc,um,us}, [13..15]=pad
__device__ __align__(16) float2 g_pack[32 * 16];  // 4 KB

__device__ __forceinline__ float softplusf(float x) {
    return fmaxf(x, 0.0f) + log1pf(expf(-fabsf(x)));
}
__device__ __forceinline__ u64 fma2(u64 a, u64 b, u64 c) {
    u64 d; asm("fma.rn.f32x2 %0,%1,%2,%3;" : "=l"(d) : "l"(a), "l"(b), "l"(c)); return d;
}
__device__ __forceinline__ u64 add2(u64 a, u64 b) {
    u64 d; asm("add.rn.f32x2 %0,%1,%2;" : "=l"(d) : "l"(a), "l"(b)); return d;
}
__device__ __forceinline__ u64 pack2(float lo, float hi) {
    u64 d; asm("mov.b64 %0,{%1,%2};" : "=l"(d) : "f"(lo), "f"(hi)); return d;
}
__device__ __forceinline__ void unpack2(float& lo, float& hi, u64 v) {
    asm("mov.b64 {%0,%1},%2;" : "=f"(lo), "=f"(hi) : "l"(v));
}

// ---------------------------------------------------------------------------
// Kernel A: detect ei dtype + build packed weight record (1 warp)
// ---------------------------------------------------------------------------
__global__ void prep_kernel(const int* __restrict__ ei32,
                            const float* __restrict__ W1,
                            const float* __restrict__ b1,
                            const float* __restrict__ W2,
                            const float* __restrict__ b2,
                            const float* __restrict__ Wc,
                            const float* __restrict__ Wmu,
                            const float* __restrict__ Wsig)
{
    const int k = threadIdx.x;  // 32 threads; k = hidden index j
    if (k == 0) {
        int z = 0;
        #pragma unroll
        for (int i = 1; i < 64; i += 2) z |= ei32[i];
        g_ei_is64 = (z == 0) ? 1 : 0;
        g_S = 0.0f;
    }
    float uc = 0.f, um = 0.f, us = 0.f;
    #pragma unroll
    for (int m = 0; m < HID; m++) {
        const float w = W2[k * HID + m];
        uc = fmaf(w, Wc[NODE_F + m],   uc);
        um = fmaf(w, Wmu[NODE_F + m],  um);
        us = fmaf(w, Wsig[NODE_F + m], us);
    }
    float2* R = g_pack + k * 16;
    #pragma unroll
    for (int d = 0; d < D_IN; d++) {
        const float w = W1[d * HID + k];
        R[d] = make_float2(w, w);
    }
    R[9]  = make_float2(b1[k], b1[k]);
    R[10] = make_float2(0.5f * uc, 0.5f * uc);
    R[11] = make_float2(0.5f * um, 0.5f * um);
    R[12] = make_float2(0.5f * us, 0.5f * us);
    R[13] = make_float2(0.f, 0.f);
    R[14] = make_float2(0.f, 0.f);
    R[15] = make_float2(0.f, 0.f);

    // scalar b2 projections via warp reduce
    float pc = b2[k] * Wc[NODE_F + k];
    float pm = b2[k] * Wmu[NODE_F + k];
    float ps = b2[k] * Wsig[NODE_F + k];
    #pragma unroll
    for (int off = 16; off > 0; off >>= 1) {
        pc += __shfl_xor_sync(0xffffffffu, pc, off);
        pm += __shfl_xor_sync(0xffffffffu, pm, off);
        ps += __shfl_xor_sync(0xffffffffu, ps, off);
    }
    if (k == 0) { g_sc = pc; g_sm = pm; g_ss = ps; }
}

// ---------------------------------------------------------------------------
// Kernel B: zero accumulators (4 MB)
// ---------------------------------------------------------------------------
__global__ void zero_kernel() {
    const int i = blockIdx.x * blockDim.x + threadIdx.x;
    if (i < N_NODES) g_acc[i] = make_float4(0.f, 0.f, 0.f, 0.f);
}

// ---------------------------------------------------------------------------
// Kernel C: per-edge MLP + projected scatter, 4 edges/thread via f32x2
// ---------------------------------------------------------------------------
__global__ __launch_bounds__(256) void edge_kernel(
    const float* __restrict__ x,
    const void* __restrict__ ei_raw,
    const float* __restrict__ ea)
{
    __shared__ __align__(16) float2 sP[32 * 16];  // 4 KB
    {
        const float4* src = reinterpret_cast<const float4*>(g_pack);
        float4* dst = reinterpret_cast<float4*>(sP);
        dst[threadIdx.x] = src[threadIdx.x];  // 256 * 16B = 4 KB exactly
    }
    __syncthreads();

    const int t = blockIdx.x * blockDim.x + threadIdx.x;
    if (t * 4 >= N_EDGES) return;

    int r[4], c[4];
    if (g_ei_is64) {
        const longlong2* ei = (const longlong2*)ei_raw;
        longlong2 r01 = __ldg(ei + t * 2), r23 = __ldg(ei + t * 2 + 1);
        longlong2 c01 = __ldg(ei + N_EDGES / 2 + t * 2), c23 = __ldg(ei + N_EDGES / 2 + t * 2 + 1);
        r[0] = (int)r01.x; r[1] = (int)r01.y; r[2] = (int)r23.x; r[3] = (int)r23.y;
        c[0] = (int)c01.x; c[1] = (int)c01.y; c[2] = (int)c23.x; c[3] = (int)c23.y;
    } else {
        const int4* ei = (const int4*)ei_raw;
        int4 rv = __ldg(ei + t);
        int4 cv = __ldg(ei + N_EDGES / 4 + t);
        r[0] = rv.x; r[1] = rv.y; r[2] = rv.z; r[3] = rv.w;
        c[0] = cv.x; c[1] = cv.y; c[2] = cv.z; c[3] = cv.w;
    }
    const float4 ev = __ldg(reinterpret_cast<const float4*>(ea) + t);

    const float4* x4 = reinterpret_cast<const float4*>(x);
    float4 xr0 = __ldg(x4 + r[0]), xr1 = __ldg(x4 + r[1]);
    float4 xr2 = __ldg(x4 + r[2]), xr3 = __ldg(x4 + r[3]);
    float4 xc0 = __ldg(x4 + c[0]), xc1 = __ldg(x4 + c[1]);
    float4 xc2 = __ldg(x4 + c[2]), xc3 = __ldg(x4 + c[3]);

    // pair0 = edges {0,1}, pair1 = edges {2,3}; in[d] = {feat_lo, feat_hi}
    u64 in0[D_IN], in1[D_IN];
    in0[0] = pack2(xr0.x, xr1.x); in0[1] = pack2(xr0.y, xr1.y);
    in0[2] = pack2(xr0.z, xr1.z); in0[3] = pack2(xr0.w, xr1.w);
    in0[4] = pack2(xc0.x, xc1.x); in0[5] = pack2(xc0.y, xc1.y);
    in0[6] = pack2(xc0.z, xc1.z); in0[7] = pack2(xc0.w, xc1.w);
    in0[8] = pack2(ev.x, ev.y);
    in1[0] = pack2(xr2.x, xr3.x); in1[1] = pack2(xr2.y, xr3.y);
    in1[2] = pack2(xr2.z, xr3.z); in1[3] = pack2(xr2.w, xr3.w);
    in1[4] = pack2(xc2.x, xc3.x); in1[5] = pack2(xc2.y, xc3.y);
    in1[6] = pack2(xc2.z, xc3.z); in1[7] = pack2(xc2.w, xc3.w);
    in1[8] = pack2(ev.z, ev.w);

    const u64 ABS = 0x7FFFFFFF7FFFFFFFULL;
    u64 hc0 = 0, hm0 = 0, hs0 = 0, hc1 = 0, hm1 = 0, hs1 = 0;

    #pragma unroll
    for (int j = 0; j < HID; j++) {
        const u64* R = reinterpret_cast<const u64*>(sP + j * 16);
        const u64 b = R[9];
        u64 a0 = b, a1 = b;
        #pragma unroll
        for (int d = 0; d < D_IN; d++) {
            const u64 w = R[d];
            a0 = fma2(in0[d], w, a0);
            a1 = fma2(in1[d], w, a1);
        }
        // relu folded: h = 0.5*(a+|a|); 0.5 already in uc/um/us
        const u64 t0 = add2(a0, a0 & ABS);
        const u64 t1 = add2(a1, a1 & ABS);
        const u64 uc = R[10], um = R[11], us = R[12];
        hc0 = fma2(t0, uc, hc0); hm0 = fma2(t0, um, hm0); hs0 = fma2(t0, us, hs0);
        hc1 = fma2(t1, uc, hc1); hm1 = fma2(t1, um, hm1); hs1 = fma2(t1, us, hs1);
    }

    float hcv[4], hmv[4], hsv[4];
    unpack2(hcv[0], hcv[1], hc0); unpack2(hcv[2], hcv[3], hc1);
    unpack2(hmv[0], hmv[1], hm0); unpack2(hmv[2], hmv[3], hm1);
    unpack2(hsv[0], hsv[1], hs0); unpack2(hsv[2], hsv[3], hs1);

    #pragma unroll
    for (int i = 0; i < 4; i++) {
        asm volatile("red.global.add.v4.f32 [%0], {%1, %2, %3, %4};"
                     :: "l"(&g_acc[r[i]]),
                        "f"(hcv[i]), "f"(hmv[i]), "f"(hsv[i]), "f"(1.0f)
                     : "memory");
    }
}

// ---------------------------------------------------------------------------
// Kernel D: per-node heads + conc sum
// ---------------------------------------------------------------------------
__global__ __launch_bounds__(256) void node_kernel(
    const float* __restrict__ x,
    const float* __restrict__ Wc,  const float* __restrict__ bc,
    const float* __restrict__ Wmu, const float* __restrict__ bmu,
    const float* __restrict__ Wsig,const float* __restrict__ bsig,
    const float* __restrict__ high,
    float* __restrict__ out)
{
    __shared__ float sWarp[8];
    const int i = blockIdx.x * blockDim.x + threadIdx.x;

    float concv = 0.0f;
    if (i < N_NODES) {
        const float4 a  = g_acc[i];
        const float4 xi = __ldg(reinterpret_cast<const float4*>(x) + i);

        const float craw = xi.x * __ldg(Wc+0) + xi.y * __ldg(Wc+1)
                         + xi.z * __ldg(Wc+2) + xi.w * __ldg(Wc+3)
                         + a.x + a.w * g_sc + __ldg(bc) + 1e-10f;
        concv = softplusf(craw);
        g_conc[i] = concv;

        const int p = i % NN;
        if (p >= NN - NF) {
            const float mraw = xi.x * __ldg(Wmu+0) + xi.y * __ldg(Wmu+1)
                             + xi.z * __ldg(Wmu+2) + xi.w * __ldg(Wmu+3)
                             + a.y + a.w * g_sm + __ldg(bmu) + 1e-20f;
            const float sraw = xi.x * __ldg(Wsig+0) + xi.y * __ldg(Wsig+1)
                             + xi.z * __ldg(Wsig+2) + xi.w * __ldg(Wsig+3)
                             + a.z + a.w * g_ss + __ldg(bsig) + 1e-20f;
            const float alpha = softplusf(mraw) + 1e-20f;
            const float beta  = softplusf(sraw) + 1e-20f;
            const int g = i / NN;
            const int j = p - (NN - NF);
            out[g * OUT_C + NN + j] = alpha / (alpha + beta) * __ldg(high + j);
        }
    }

    float s = concv;
    #pragma unroll
    for (int off = 16; off > 0; off >>= 1) s += __shfl_xor_sync(0xffffffffu, s, off);
    if ((threadIdx.x & 31) == 0) sWarp[threadIdx.x >> 5] = s;
    __syncthreads();
    if (threadIdx.x == 0) {
        float tsum = 0.f;
        #pragma unroll
        for (int w = 0; w < 8; w++) tsum += sWarp[w];
        atomicAdd(&g_S, tsum);
    }
}

// ---------------------------------------------------------------------------
// Kernel E: normalize conc
// ---------------------------------------------------------------------------
__global__ void final_kernel(float* __restrict__ out) {
    const int i = blockIdx.x * blockDim.x + threadIdx.x;
    if (i >= N_NODES) return;
    const float invS = 1.0f / (g_S + 1e-20f);
    out[(i / NN) * OUT_C + (i % NN)] = g_conc[i] * invS;
}

// ---------------------------------------------------------------------------
extern "C" void kernel_launch(void* const* d_in, const int* in_sizes, int n_in,
                              void* d_out, int out_size) {
    const float* x    = (const float*)d_in[0];
    const void*  ei   = d_in[1];
    const float* ea   = (const float*)d_in[2];
    const float* high = (const float*)d_in[3];
    const float* W1   = (const float*)d_in[4];
    const float* b1   = (const float*)d_in[5];
    const float* W2   = (const float*)d_in[6];
    const float* b2   = (const float*)d_in[7];
    const float* Wc   = (const float*)d_in[8];
    const float* bc   = (const float*)d_in[9];
    const float* Wmu  = (const float*)d_in[10];
    const float* bmu  = (const float*)d_in[11];
    const float* Wsig = (const float*)d_in[12];
    const float* bsig = (const float*)d_in[13];
    float* out = (float*)d_out;

    prep_kernel<<<1, 32>>>((const int*)ei, W1, b1, W2, b2, Wc, Wmu, Wsig);
    zero_kernel<<<(N_NODES + 255) / 256, 256>>>();
    edge_kernel<<<(N_EDGES / 4 + 255) / 256, 256>>>(x, ei, ea);
    node_kernel<<<(N_NODES + 255) / 256, 256>>>(x, Wc, bc, Wmu, bmu, Wsig, bsig, high, out);
    final_kernel<<<(N_NODES + 255) / 256, 256>>>(out);
}